// round 14
// baseline (speedup 1.0000x reference)
#include <cuda_runtime.h>
#include <cuda_fp16.h>
#include <cstdint>

#define IN_F   8192
#define OUT_F  8192
#define NBLK   64
#define M_TILE 32
#define GRID_Y 9
#define TOT_TILES 256               // 8192 / 32 token tiles per feature block

#define ROW_B   272                 // W fp16 padded row stride bytes
#define W_B     (128 * ROW_B)       // 34816
#define XROW_B  576                 // interleaved fp32 X row stride bytes
#define XSTG    (M_TILE * XROW_B)   // 18432 per stage
#define NSTAGE  4

#define OFF_BIAS 0
#define OFF_W    1024
#define OFF_X    (1024 + W_B)               // 35840
#define SMEM_TOTAL (OFF_X + NSTAGE * XSTG)  // 109568 -> 2 CTAs/SM

// pre-converted W blocks: [b] -> 128x128 fp16 padded tile
__device__ __align__(16) char g_wcvt[NBLK * W_B];

__device__ __forceinline__ uint32_t smem_u32(const void* p) {
    uint32_t a;
    asm("{ .reg .u64 t; cvta.to.shared.u64 t, %1; cvt.u32.u64 %0, t; }" : "=r"(a) : "l"(p));
    return a;
}
__device__ __forceinline__ uint32_t pack_h2(float a, float b) {
    __half2 h = __float22half2_rn(make_float2(a, b));
    return *reinterpret_cast<uint32_t*>(&h);
}
__device__ __forceinline__ float4 lds128(uint32_t a) {
    float4 v;
    asm volatile("ld.shared.v4.f32 {%0,%1,%2,%3}, [%4];"
                 : "=f"(v.x), "=f"(v.y), "=f"(v.z), "=f"(v.w) : "r"(a));
    return v;
}
__device__ __forceinline__ void ldsm_x4(uint32_t& r0, uint32_t& r1, uint32_t& r2, uint32_t& r3,
                                        uint32_t addr) {
    asm volatile("ldmatrix.sync.aligned.m8n8.x4.shared.b16 {%0,%1,%2,%3}, [%4];"
                 : "=r"(r0), "=r"(r1), "=r"(r2), "=r"(r3) : "r"(addr));
}
__device__ __forceinline__ void mma_f16(float* d, const uint32_t* a, uint32_t b0, uint32_t b1) {
    asm volatile(
        "mma.sync.aligned.m16n8k16.row.col.f32.f16.f16.f32 "
        "{%0,%1,%2,%3}, {%4,%5,%6,%7}, {%8,%9}, {%0,%1,%2,%3};"
        : "+f"(d[0]), "+f"(d[1]), "+f"(d[2]), "+f"(d[3])
        : "r"(a[0]), "r"(a[1]), "r"(a[2]), "r"(a[3]), "r"(b0), "r"(b1));
}
__device__ __forceinline__ float wire_act(float z) {
    float s, e;
    asm("sin.approx.ftz.f32 %0, %1;" : "=f"(s) : "f"(z * 30.0f));
    float t = -0.01442695040888963f * z * z;   // -0.01 * log2(e) * z^2
    asm("ex2.approx.ftz.f32 %0, %1;" : "=f"(e) : "f"(t));
    return s * e;
}
__device__ __forceinline__ void stg_cs_v2(float* p, float a, float b) {
    asm volatile("st.global.cs.v2.f32 [%0], {%1,%2};" :: "l"(p), "f"(a), "f"(b) : "memory");
}

// ------------- prep: convert W diag blocks to fp16 padded tiles -------------
__global__ void __launch_bounds__(128)
wcvt_kernel(const float* __restrict__ w)
{
    const int b = blockIdx.x;
    const int t = threadIdx.x;
    const int r0 = t >> 5;
    const int c4 = t & 31;
    const float* wrow = w + (size_t)(b * 128) * IN_F + (size_t)b * 128;
    char* dst = g_wcvt + (size_t)b * W_B;
    #pragma unroll 4
    for (int r = r0; r < 128; r += 4) {
        float4 v = *(const float4*)(wrow + (size_t)r * IN_F + (c4 << 2));
        *(uint2*)(dst + r * ROW_B + (c4 << 3)) =
            make_uint2(pack_h2(v.x, v.y), pack_h2(v.z, v.w));
    }
}

// ------------- main kernel: B-in-regs, interleaved X, 1 barrier/tile -------------
__global__ void __launch_bounds__(256, 2)
siren_ilv_kernel(const float* __restrict__ x, const float* __restrict__ bias,
                 float* __restrict__ out)
{
    extern __shared__ char smem[];
    const uint32_t sbase = smem_u32(smem);
    const int tid = threadIdx.x;
    const int wid = tid >> 5;
    const int lid = tid & 31;
    const int b = blockIdx.x;

    const int yi = blockIdx.y;
    const int tstart = (TOT_TILES * yi) / GRID_Y;
    const int tend   = (TOT_TILES * (yi + 1)) / GRID_Y;
    const int ntiles = tend - tstart;

    // ---- W tile via cp.async (group 0) ----
    {
        const char* wsrc = g_wcvt + (size_t)b * W_B;
        #pragma unroll 9
        for (int i = tid; i < W_B / 16; i += 256) {
            uint32_t dst = sbase + OFF_W + i * 16;
            asm volatile("cp.async.cg.shared.global [%0], [%1], 16;"
                         :: "r"(dst), "l"(wsrc + i * 16) : "memory");
        }
        asm volatile("cp.async.commit_group;" ::: "memory");
    }
    if (tid < 128) ((float*)(smem + OFF_BIAS))[tid] = bias[b * 128 + tid];

    const float* xbase = x + (size_t)b * 128;
    // Interleaved 8B cp.async: pair q of k-group g -> byte (q&3)*16 + (q>>2)*8.
    // One LDS.128 then yields {k=c, c+1, c+8, c+9} for the mma A fragment.
    #define ISSUE_X(tj_, buf_)                                                      \
        {                                                                           \
            const float* src_ = xbase + (size_t)((tj_) * M_TILE) * IN_F;            \
            const uint32_t db_ = sbase + OFF_X + (buf_) * XSTG;                     \
            _Pragma("unroll")                                                       \
            for (int j_ = 0; j_ < 8; j_++) {                                        \
                int idx_ = tid + j_ * 256;                                          \
                int r_ = idx_ >> 6;          /* 64 pairs per row */                 \
                int qg_ = idx_ & 63;                                                \
                int g_ = qg_ >> 3, q_ = qg_ & 7;                                    \
                uint32_t d_ = db_ + r_ * XROW_B + g_ * 64 + (q_ & 3) * 16 + (q_ >> 2) * 8; \
                asm volatile("cp.async.ca.shared.global [%0], [%1], 8;"             \
                             :: "r"(d_), "l"(src_ + (size_t)r_ * IN_F + g_ * 16 + q_ * 2) \
                             : "memory");                                           \
            }                                                                       \
        }

    // prologue: NSTAGE-1 stages in flight
    #pragma unroll
    for (int p = 0; p < NSTAGE - 1; p++) {
        ISSUE_X(tstart + p, p);
        asm volatile("cp.async.commit_group;" ::: "memory");
    }

    // ---- warp tiling: 8 warps -> 2 (m16) x 4 (n32) ----
    const int M0 = (wid & 1) * 16;
    const int N0 = (wid >> 1) * 32;
    const uint32_t offB = (uint32_t)((((lid >> 4) & 1) * 8 + (lid & 7)) * ROW_B
                                     + ((lid >> 3) & 1) * 16);
    const uint32_t bB = sbase + OFF_W + (uint32_t)(N0 * ROW_B) + offB;
    const uint32_t aoff = (uint32_t)((M0 + (lid >> 2)) * XROW_B + (lid & 3) * 16);
    const float* bs = (const float*)(smem + OFF_BIAS);
    const int lrow = lid >> 2;
    const int lcol = (lid & 3) * 2;

    // ---- hoist all B fragments into registers (W constant across tiles) ----
    asm volatile("cp.async.wait_group %0;" :: "n"(NSTAGE - 1) : "memory");   // W retired
    __syncthreads();
    uint32_t breg[8][8];
    #pragma unroll
    for (int ks = 0; ks < 8; ks++) {
        const uint32_t kb = (uint32_t)(ks * 32);
        ldsm_x4(breg[ks][0], breg[ks][1], breg[ks][2], breg[ks][3], bB + kb);
        ldsm_x4(breg[ks][4], breg[ks][5], breg[ks][6], breg[ks][7],
                bB + kb + (uint32_t)(16 * ROW_B));
    }

    #pragma unroll 1
    for (int i = 0; i < ntiles; i++) {
        // X_i ready when <= NSTAGE-2 groups outstanding
        asm volatile("cp.async.wait_group %0;" :: "n"(NSTAGE - 2) : "memory");
        __syncthreads();   // also: all warps finished reading buf (i-1)&3 last iter

        // issue tile i+NSTAGE-1 into buf (i-1)&3 (safe after the barrier above)
        if (i + NSTAGE - 1 < ntiles)
            ISSUE_X(tstart + i + NSTAGE - 1, (i + NSTAGE - 1) & (NSTAGE - 1));
        asm volatile("cp.async.commit_group;" ::: "memory");

        const uint32_t aS = sbase + OFF_X + (i & (NSTAGE - 1)) * XSTG + aoff;

        float acc[4][4];
        #pragma unroll
        for (int nt = 0; nt < 4; nt++)
            #pragma unroll
            for (int k = 0; k < 4; k++) acc[nt][k] = 0.0f;

        #pragma unroll
        for (int ks = 0; ks < 8; ks++) {
            const uint32_t ka = (uint32_t)(ks * 64);
            float4 r0 = lds128(aS + ka);                    // row:    c,c+1,c+8,c+9
            float4 r1 = lds128(aS + ka + 8 * XROW_B);       // row+8:  c,c+1,c+8,c+9
            uint32_t af[4];
            af[0] = pack_h2(r0.x, r0.y);
            af[1] = pack_h2(r1.x, r1.y);
            af[2] = pack_h2(r0.z, r0.w);
            af[3] = pack_h2(r1.z, r1.w);
            mma_f16(acc[0], af, breg[ks][0], breg[ks][1]);
            mma_f16(acc[1], af, breg[ks][2], breg[ks][3]);
            mma_f16(acc[2], af, breg[ks][4], breg[ks][5]);
            mma_f16(acc[3], af, breg[ks][6], breg[ks][7]);
        }

        // ---- epilogue: bias + wire activation + streaming store ----
        const int rbase = (tstart + i) * M_TILE + M0 + lrow;
        #pragma unroll
        for (int nt = 0; nt < 4; nt++) {
            const int nn = N0 + nt * 8 + lcol;
            float* p0 = out + (size_t)rbase * OUT_F + (size_t)b * 128 + nn;
            stg_cs_v2(p0, wire_act(acc[nt][0] + bs[nn]), wire_act(acc[nt][1] + bs[nn + 1]));
            stg_cs_v2(p0 + (size_t)8 * OUT_F,
                      wire_act(acc[nt][2] + bs[nn]), wire_act(acc[nt][3] + bs[nn + 1]));
        }
    }
}

extern "C" void kernel_launch(void* const* d_in, const int* in_sizes, int n_in,
                              void* d_out, int out_size)
{
    const float* x    = (const float*)d_in[0];
    const float* w    = (const float*)d_in[1];
    const float* bias = (const float*)d_in[2];
    float* out = (float*)d_out;

    wcvt_kernel<<<NBLK, 128>>>(w);

    cudaFuncSetAttribute(siren_ilv_kernel,
                         cudaFuncAttributeMaxDynamicSharedMemorySize, SMEM_TOTAL);
    dim3 grid(NBLK, GRID_Y);
    siren_ilv_kernel<<<grid, 256, SMEM_TOTAL>>>(x, bias, out);
}

// round 15
// speedup vs baseline: 1.0088x; 1.0088x over previous
#include <cuda_runtime.h>
#include <cuda_fp16.h>
#include <cstdint>

#define IN_F   8192
#define OUT_F  8192
#define NBLK   64
#define M_TILE 32
#define GRID_Y 9
#define TOT_TILES 256               // 8192 / 32 token tiles per feature block

#define ROW_B   272                 // fp16 padded row stride bytes (136 halves)
#define W_B     (128 * ROW_B)       // 34816
#define XSTG    (M_TILE * ROW_B)    // 8704: one 32x128 fp16 X tile
#define NSTAGE  2

#define OFF_BIAS 0
#define OFF_W    1024
#define OFF_X    (1024 + W_B)               // 35840
#define SMEM_TOTAL (OFF_X + NSTAGE * XSTG)  // 53248 -> 2 CTAs/SM

// pre-converted W blocks: [b] -> 128x128 fp16 padded tile
__device__ __align__(16) char g_wcvt[NBLK * W_B];

__device__ __forceinline__ uint32_t smem_u32(const void* p) {
    uint32_t a;
    asm("{ .reg .u64 t; cvta.to.shared.u64 t, %1; cvt.u32.u64 %0, t; }" : "=r"(a) : "l"(p));
    return a;
}
__device__ __forceinline__ uint32_t pack_h2(float a, float b) {
    __half2 h = __float22half2_rn(make_float2(a, b));
    return *reinterpret_cast<uint32_t*>(&h);
}
__device__ __forceinline__ void ldsm_x4(uint32_t& r0, uint32_t& r1, uint32_t& r2, uint32_t& r3,
                                        uint32_t addr) {
    asm volatile("ldmatrix.sync.aligned.m8n8.x4.shared.b16 {%0,%1,%2,%3}, [%4];"
                 : "=r"(r0), "=r"(r1), "=r"(r2), "=r"(r3) : "r"(addr));
}
__device__ __forceinline__ void mma_f16(float* d, const uint32_t* a, uint32_t b0, uint32_t b1) {
    asm volatile(
        "mma.sync.aligned.m16n8k16.row.col.f32.f16.f16.f32 "
        "{%0,%1,%2,%3}, {%4,%5,%6,%7}, {%8,%9}, {%0,%1,%2,%3};"
        : "+f"(d[0]), "+f"(d[1]), "+f"(d[2]), "+f"(d[3])
        : "r"(a[0]), "r"(a[1]), "r"(a[2]), "r"(a[3]), "r"(b0), "r"(b1));
}
__device__ __forceinline__ float wire_act(float z) {
    float s, e;
    asm("sin.approx.ftz.f32 %0, %1;" : "=f"(s) : "f"(z * 30.0f));
    float t = -0.01442695040888963f * z * z;   // -0.01 * log2(e) * z^2
    asm("ex2.approx.ftz.f32 %0, %1;" : "=f"(e) : "f"(t));
    return s * e;
}
__device__ __forceinline__ void stg_cs_v2(float* p, float a, float b) {
    asm volatile("st.global.cs.v2.f32 [%0], {%1,%2};" :: "l"(p), "f"(a), "f"(b) : "memory");
}
__device__ __forceinline__ float4 ldg_cs_v4(const float* p) {
    float4 v;
    asm volatile("ld.global.cs.v4.f32 {%0,%1,%2,%3}, [%4];"
                 : "=f"(v.x), "=f"(v.y), "=f"(v.z), "=f"(v.w) : "l"(p));
    return v;
}

// ------------- prep: convert W diag blocks to fp16 padded tiles -------------
__global__ void __launch_bounds__(128)
wcvt_kernel(const float* __restrict__ w)
{
    const int b = blockIdx.x;
    const int t = threadIdx.x;
    const int r0 = t >> 5;
    const int c4 = t & 31;
    const float* wrow = w + (size_t)(b * 128) * IN_F + (size_t)b * 128;
    char* dst = g_wcvt + (size_t)b * W_B;
    #pragma unroll 4
    for (int r = r0; r < 128; r += 4) {
        float4 v = *(const float4*)(wrow + (size_t)r * IN_F + (c4 << 2));
        *(uint2*)(dst + r * ROW_B + (c4 << 3)) =
            make_uint2(pack_h2(v.x, v.y), pack_h2(v.z, v.w));
    }
}

// ------------- main kernel: fp16 X staging, ldmatrix A, B-in-regs -------------
__global__ void __launch_bounds__(256, 2)
siren_h16_kernel(const float* __restrict__ x, const float* __restrict__ bias,
                 float* __restrict__ out)
{
    extern __shared__ char smem[];
    const uint32_t sbase = smem_u32(smem);
    const int tid = threadIdx.x;
    const int wid = tid >> 5;
    const int lid = tid & 31;
    const int b = blockIdx.x;

    const int yi = blockIdx.y;
    const int tstart = (TOT_TILES * yi) / GRID_Y;
    const int tend   = (TOT_TILES * (yi + 1)) / GRID_Y;
    const int ntiles = tend - tstart;

    // ---- W tile via cp.async (group 0) ----
    {
        const char* wsrc = g_wcvt + (size_t)b * W_B;
        #pragma unroll 9
        for (int i = tid; i < W_B / 16; i += 256) {
            uint32_t dst = sbase + OFF_W + i * 16;
            asm volatile("cp.async.cg.shared.global [%0], [%1], 16;"
                         :: "r"(dst), "l"(wsrc + i * 16) : "memory");
        }
        asm volatile("cp.async.commit_group;" ::: "memory");
    }
    if (tid < 128) ((float*)(smem + OFF_BIAS))[tid] = bias[b * 128 + tid];

    // ---- X staging assignment: thread -> (row, 16-float chunk) ----
    const int xrow = tid >> 3;          // 0..31
    const int xch  = tid & 7;           // 0..7
    const float* xsrc0 = x + (size_t)b * 128 + (size_t)xrow * IN_F + xch * 16;
    const uint32_t sts_addr = sbase + OFF_X + (uint32_t)(xrow * ROW_B + xch * 32);

    float4 ld[4];
    uint32_t pk[8];
    #define LDG_X(tj_)                                                          \
        {                                                                       \
            const float* s_ = xsrc0 + (size_t)((tj_) * M_TILE) * IN_F;          \
            ld[0] = ldg_cs_v4(s_);                                              \
            ld[1] = ldg_cs_v4(s_ + 4);                                          \
            ld[2] = ldg_cs_v4(s_ + 8);                                          \
            ld[3] = ldg_cs_v4(s_ + 12);                                         \
        }
    #define PACK_X()                                                            \
        {                                                                       \
            _Pragma("unroll")                                                   \
            for (int q_ = 0; q_ < 4; q_++) {                                    \
                pk[q_ * 2 + 0] = pack_h2(ld[q_].x, ld[q_].y);                   \
                pk[q_ * 2 + 1] = pack_h2(ld[q_].z, ld[q_].w);                   \
            }                                                                   \
        }
    #define STS_X(buf_)                                                        \
        {                                                                      \
            uint32_t d_ = sts_addr + (buf_) * XSTG;                            \
            asm volatile("st.shared.v4.b32 [%0], {%1,%2,%3,%4};"               \
                         :: "r"(d_), "r"(pk[0]), "r"(pk[1]), "r"(pk[2]), "r"(pk[3]) : "memory"); \
            asm volatile("st.shared.v4.b32 [%0], {%1,%2,%3,%4};"               \
                         :: "r"(d_ + 16), "r"(pk[4]), "r"(pk[5]), "r"(pk[6]), "r"(pk[7]) : "memory"); \
        }

    // prologue: tile0 -> buf0; tile1 packed in regs
    LDG_X(tstart + 0); PACK_X(); STS_X(0);
    LDG_X(tstart + 1);

    // ---- warp tiling: 8 warps -> 2 (m16) x 4 (n32) ----
    const int M0 = (wid & 1) * 16;
    const int N0 = (wid >> 1) * 32;
    const uint32_t offB = (uint32_t)((((lid >> 4) & 1) * 8 + (lid & 7)) * ROW_B
                                     + ((lid >> 3) & 1) * 16);
    const uint32_t bB = sbase + OFF_W + (uint32_t)(N0 * ROW_B) + offB;
    const uint32_t offA = (uint32_t)((M0 + (lid & 15)) * ROW_B + (lid >> 4) * 16);
    const float* bs = (const float*)(smem + OFF_BIAS);
    const int lrow = lid >> 2;
    const int lcol = (lid & 3) * 2;

    // ---- W retired; hoist B fragments into registers ----
    asm volatile("cp.async.wait_group 0;" ::: "memory");
    __syncthreads();                       // also makes buf0 STS visible
    uint32_t breg[8][8];
    #pragma unroll
    for (int ks = 0; ks < 8; ks++) {
        const uint32_t kb = (uint32_t)(ks * 32);
        ldsm_x4(breg[ks][0], breg[ks][1], breg[ks][2], breg[ks][3], bB + kb);
        ldsm_x4(breg[ks][4], breg[ks][5], breg[ks][6], breg[ks][7],
                bB + kb + (uint32_t)(16 * ROW_B));
    }
    PACK_X();                              // tile1 -> pk

    #pragma unroll 1
    for (int i = 0; i < ntiles; i++) {
        // store tile i+1 (in pk) into buf (i+1)&1  (read last at iter i-1; safe)
        if (i + 1 < ntiles) STS_X((i + 1) & 1);
        // prefetch tile i+2
        if (i + 2 < ntiles) LDG_X(tstart + i + 2);

        const uint32_t aS = sbase + OFF_X + (i & 1) * XSTG + offA;

        float acc[4][4];
        #pragma unroll
        for (int nt = 0; nt < 4; nt++)
            #pragma unroll
            for (int k = 0; k < 4; k++) acc[nt][k] = 0.0f;

        #pragma unroll
        for (int ks = 0; ks < 8; ks++) {
            uint32_t af[4];
            ldsm_x4(af[0], af[1], af[2], af[3], aS + (uint32_t)(ks * 32));
            mma_f16(acc[0], af, breg[ks][0], breg[ks][1]);
            mma_f16(acc[1], af, breg[ks][2], breg[ks][3]);
            mma_f16(acc[2], af, breg[ks][4], breg[ks][5]);
            mma_f16(acc[3], af, breg[ks][6], breg[ks][7]);
        }

        PACK_X();                          // tile i+2 -> pk (LDG latency covered by MMAs)

        // ---- epilogue: bias + wire activation + streaming store ----
        const int rbase = (tstart + i) * M_TILE + M0 + lrow;
        #pragma unroll
        for (int nt = 0; nt < 4; nt++) {
            const int nn = N0 + nt * 8 + lcol;
            float* p0 = out + (size_t)rbase * OUT_F + (size_t)b * 128 + nn;
            stg_cs_v2(p0, wire_act(acc[nt][0] + bs[nn]), wire_act(acc[nt][1] + bs[nn + 1]));
            stg_cs_v2(p0 + (size_t)8 * OUT_F,
                      wire_act(acc[nt][2] + bs[nn]), wire_act(acc[nt][3] + bs[nn + 1]));
        }

        __syncthreads();   // STS(i+1) visible to all; all done reading buf i&1
    }
}

extern "C" void kernel_launch(void* const* d_in, const int* in_sizes, int n_in,
                              void* d_out, int out_size)
{
    const float* x    = (const float*)d_in[0];
    const float* w    = (const float*)d_in[1];
    const float* bias = (const float*)d_in[2];
    float* out = (float*)d_out;

    wcvt_kernel<<<NBLK, 128>>>(w);

    cudaFuncSetAttribute(siren_h16_kernel,
                         cudaFuncAttributeMaxDynamicSharedMemorySize, SMEM_TOTAL);
    dim3 grid(NBLK, GRID_Y);
    siren_h16_kernel<<<grid, 256, SMEM_TOTAL>>>(x, bias, out);
}